// round 1
// baseline (speedup 1.0000x reference)
#include <cuda_runtime.h>
#include <math.h>

#define TOKENS 131072
#define HIDDEN 2048
#define NEXP 64
#define TOPK 8
#define ROUTER_SCALE 2.5f

#define BT 128      // tokens per CTA
#define KT 32       // K tile
#define NTHREADS 256

// Dynamic shared memory layout (overlapped):
//   during GEMM:    sx[128][32] (4096 f)  | sw[64][33] (2112 f)
//   during epilogue: slog[128][65] (8320 f) reuses the same buffer
// total = 8320 floats = 33280 bytes (< 48KB default dynamic limit)
#define SX_STRIDE 32
#define SW_STRIDE 33
#define SW_OFF    (BT * SX_STRIDE)           // 4096
#define SLOG_STRIDE 65
#define SMEM_FLOATS (BT * SLOG_STRIDE)       // 8320

__global__ __launch_bounds__(NTHREADS, 2)
void gate_kernel(const float* __restrict__ x,
                 const float* __restrict__ w,
                 const float* __restrict__ bias,
                 float* __restrict__ out)
{
    extern __shared__ float smem[];
    float* sx = smem;            // [BT][SX_STRIDE]
    float* sw = smem + SW_OFF;   // [NEXP][SW_STRIDE]
    float* slog = smem;          // [BT][SLOG_STRIDE] (reused after GEMM)

    __shared__ float sb[NEXP];

    const int t = threadIdx.x;
    const int eg = t & 15;       // expert group -> experts e0..e0+3
    const int tg = t >> 4;       // token group  -> rows   r0..r0+7
    const int e0 = eg * 4;
    const int r0 = tg * 8;
    const int tok0 = blockIdx.x * BT;

    if (t < NEXP) sb[t] = bias[t];

    // master accumulators: 8 tokens x 4 experts
    float acc[8][4];
#pragma unroll
    for (int i = 0; i < 8; i++)
#pragma unroll
        for (int j = 0; j < 4; j++) acc[i][j] = 0.0f;

    for (int k0 = 0; k0 < HIDDEN; k0 += KT) {
        // ---- load x tile: 128x32 floats = 1024 float4, 4 per thread ----
#pragma unroll
        for (int i = 0; i < 4; i++) {
            int idx = t + i * NTHREADS;      // 0..1023
            int r = idx >> 3;                // 8 float4 per row
            int c = (idx & 7) * 4;
            float4 v = *(const float4*)(x + (size_t)(tok0 + r) * HIDDEN + k0 + c);
            *(float4*)(sx + r * SX_STRIDE + c) = v;
        }
        // ---- load w tile: 64x32 floats = 512 float4, 2 per thread ----
#pragma unroll
        for (int i = 0; i < 2; i++) {
            int idx = t + i * NTHREADS;      // 0..511
            int r = idx >> 3;
            int c = (idx & 7) * 4;
            float4 v = *(const float4*)(w + (size_t)r * HIDDEN + k0 + c);
            float* p = sw + r * SW_STRIDE + c;
            p[0] = v.x; p[1] = v.y; p[2] = v.z; p[3] = v.w;
        }
        __syncthreads();

        // ---- per-tile sub-accumulator (limits serial-sum rounding error) ----
        float tacc[8][4];
#pragma unroll
        for (int i = 0; i < 8; i++)
#pragma unroll
            for (int j = 0; j < 4; j++) tacc[i][j] = 0.0f;

#pragma unroll 4
        for (int kk = 0; kk < KT; kk++) {
            float wv[4], xv[8];
#pragma unroll
            for (int j = 0; j < 4; j++) wv[j] = sw[(e0 + j) * SW_STRIDE + kk];
#pragma unroll
            for (int i = 0; i < 8; i++) xv[i] = sx[(r0 + i) * SX_STRIDE + kk];
#pragma unroll
            for (int i = 0; i < 8; i++)
#pragma unroll
                for (int j = 0; j < 4; j++)
                    tacc[i][j] = fmaf(xv[i], wv[j], tacc[i][j]);
        }
#pragma unroll
        for (int i = 0; i < 8; i++)
#pragma unroll
            for (int j = 0; j < 4; j++) acc[i][j] += tacc[i][j];

        __syncthreads();
    }

    // ---- dump logits into shared (sx/sw regions are dead now) ----
#pragma unroll
    for (int i = 0; i < 8; i++)
#pragma unroll
        for (int j = 0; j < 4; j++)
            slog[(r0 + i) * SLOG_STRIDE + (e0 + j)] = acc[i][j];
    __syncthreads();

    // ---- per-token softmax + bias-corrected top-8 ----
    if (t < BT) {
        const int row = t;
        const int token = tok0 + row;
        float* lg = slog + row * SLOG_STRIDE;

        float mx = lg[0];
#pragma unroll
        for (int e = 1; e < NEXP; e++) mx = fmaxf(mx, lg[e]);

        float sum = 0.0f;
#pragma unroll
        for (int e = 0; e < NEXP; e++) {
            float v = expf(lg[e] - mx);
            lg[e] = v;           // store exp values back (thread-private row)
            sum += v;
        }
        const float inv = 1.0f / sum;

        unsigned long long used = 0ull;
#pragma unroll
        for (int i = 0; i < TOPK; i++) {
            float best = -INFINITY;
            int bi = 0;
            for (int e = 0; e < NEXP; e++) {
                if ((used >> e) & 1ull) continue;
                float b = lg[e] * inv + sb[e];   // biased score (selection only)
                if (b > best) { best = b; bi = e; }   // strict > : lowest index wins ties
            }
            used |= (1ull << bi);
            // outputs: weights first, then indices (numeric-cast to float)
            out[(size_t)token * TOPK + i] = lg[bi] * inv * ROUTER_SCALE;
            out[(size_t)TOKENS * TOPK + (size_t)token * TOPK + i] = (float)bi;
        }
    }
}

extern "C" void kernel_launch(void* const* d_in, const int* in_sizes, int n_in,
                              void* d_out, int out_size)
{
    const float* x    = (const float*)d_in[0];
    const float* w    = (const float*)d_in[1];
    const float* bias = (const float*)d_in[2];
    float* out = (float*)d_out;

    dim3 grid(TOKENS / BT);   // 1024
    dim3 block(NTHREADS);
    size_t smem_bytes = SMEM_FLOATS * sizeof(float);   // 33280 B
    gate_kernel<<<grid, block, smem_bytes>>>(x, w, bias, out);
}

// round 5
// speedup vs baseline: 1.0256x; 1.0256x over previous
#include <cuda_runtime.h>
#include <math.h>
#include <stdint.h>

#define TOKENS 131072
#define HIDDEN 2048
#define NEXP 64
#define TOPK 8
#define ROUTER_SCALE 2.5f

#define BT 128             // tokens per CTA
#define KT 32              // K tile (matches round-1 numerics)
#define NTHREADS 256
#define NTILES (HIDDEN / KT)   // 64

// SMEM float offsets
//  staging (cp.async dst):  sxs[128][36] | sws[64][36]      = 6912 floats
//  px  (u64): pairs [64][33]  px[p*33+k] = {x[2p][k],x[2p+1][k]}  = 2112 u64
//  swd (u64): dup    [64][33] swd[e*33+k] = {w[e][k],w[e][k]}     = 2112 u64
//  epilogue slog[128][65] reuses [0, 8320) floats (staging+px head, dead)
#define XSTRIDE 36
#define WSTRIDE 36
#define STAGE_X 0
#define STAGE_W (BT * XSTRIDE)                  // 4608
#define STAGE_FLOATS (STAGE_W + NEXP * WSTRIDE) // 6912
#define PX_OFF_F  STAGE_FLOATS                  // 6912 (8B aligned: 27648 B)
#define PX_U64S   (64 * 33)                     // 2112
#define SWD_OFF_F (PX_OFF_F + PX_U64S * 2)      // 11136
#define SWD_U64S  (64 * 33)                     // 2112
#define SMEM_FLOATS (SWD_OFF_F + SWD_U64S * 2)  // 15360 floats = 61440 B
#define SLOG_STRIDE 65

typedef unsigned long long u64;

__device__ __forceinline__ u64 ffma2(u64 a, u64 b, u64 c) {
    u64 d;
    asm("fma.rn.f32x2 %0, %1, %2, %3;" : "=l"(d) : "l"(a), "l"(b), "l"(c));
    return d;
}
__device__ __forceinline__ u64 fadd2(u64 a, u64 b) {
    u64 d;
    asm("add.rn.f32x2 %0, %1, %2;" : "=l"(d) : "l"(a), "l"(b));
    return d;
}
__device__ __forceinline__ u64 pack2(float lo, float hi) {
    u64 d;
    asm("mov.b64 %0, {%1, %2};" : "=l"(d) : "f"(lo), "f"(hi));
    return d;
}
__device__ __forceinline__ void cpasync16(uint32_t dst_smem, const void* gsrc) {
    asm volatile("cp.async.ca.shared.global [%0], [%1], 16;"
                 :: "r"(dst_smem), "l"(gsrc));
}

__device__ __forceinline__ void issue_tile(uint32_t sbase, int t,
                                           const float* __restrict__ x,
                                           const float* __restrict__ w,
                                           int tok0, int k0) {
    // x tile: 128 rows x 8 float4 = 1024 chunks, 4 per thread
#pragma unroll
    for (int i = 0; i < 4; i++) {
        int idx = t + i * NTHREADS;
        int row = idx >> 3;
        int kq  = idx & 7;
        cpasync16(sbase + (uint32_t)(STAGE_X + row * XSTRIDE + kq * 4) * 4,
                  x + (size_t)(tok0 + row) * HIDDEN + k0 + kq * 4);
    }
    // w tile: 64 rows x 8 float4 = 512 chunks, 2 per thread
#pragma unroll
    for (int i = 0; i < 2; i++) {
        int idx = t + i * NTHREADS;
        int row = idx >> 3;
        int kq  = idx & 7;
        cpasync16(sbase + (uint32_t)(STAGE_W + row * WSTRIDE + kq * 4) * 4,
                  w + (size_t)row * HIDDEN + k0 + kq * 4);
    }
    asm volatile("cp.async.commit_group;" ::: "memory");
}

__global__ __launch_bounds__(NTHREADS, 2)
void gate_kernel(const float* __restrict__ x,
                 const float* __restrict__ w,
                 const float* __restrict__ bias,
                 float* __restrict__ out)
{
    extern __shared__ float smem[];
    __shared__ float sb[NEXP];

    u64* px  = reinterpret_cast<u64*>(smem + PX_OFF_F);
    u64* swd = reinterpret_cast<u64*>(smem + SWD_OFF_F);

    const int t = threadIdx.x;
    const int tok0 = blockIdx.x * BT;

    // thread tile: 4 token-pairs (8 tokens) x 4 experts (interleaved stride 16)
    const int tg = t >> 4;          // 0..15 -> pairs tg*4 .. tg*4+3
    const int eg = t & 15;          // 0..15 -> experts eg, eg+16, eg+32, eg+48
    const int p0 = tg * 4;

    if (t < NEXP) sb[t] = bias[t];

    uint32_t sbase;
    asm("{ .reg .u64 tmp; cvta.to.shared.u64 tmp, %1; cvt.u32.u64 %0, tmp; }"
        : "=r"(sbase) : "l"(smem));

    // master accumulators: lanes = (token 2p, token 2p+1); each lane's op
    // order is EXACTLY round-1's scalar order (bit-identical logits).
    u64 acc[4][4];
#pragma unroll
    for (int i = 0; i < 4; i++)
#pragma unroll
        for (int j = 0; j < 4; j++) acc[i][j] = 0ull;

    issue_tile(sbase, t, x, w, tok0, 0);   // prologue

    for (int tile = 0; tile < NTILES; tile++) {
        asm volatile("cp.async.wait_group 0;" ::: "memory");
        __syncthreads();   // staging ready; also fences last tile's compute

        // ---- repack staging -> px / swd ----
        // px: 2048 u64 (64 pairs x 32 k), 8 per thread
#pragma unroll
        for (int i = 0; i < 8; i++) {
            int idx = t + i * NTHREADS;
            int p = idx >> 5;         // 0..63
            int k = idx & 31;
            float lo = smem[STAGE_X + (2 * p)     * XSTRIDE + k];
            float hi = smem[STAGE_X + (2 * p + 1) * XSTRIDE + k];
            px[p * 33 + k] = pack2(lo, hi);
        }
        // swd: 2048 u64 (64 experts x 32 k), duplicated {w,w}
#pragma unroll
        for (int i = 0; i < 8; i++) {
            int idx = t + i * NTHREADS;
            int e = idx >> 5;         // 0..63
            int k = idx & 31;
            float v = smem[STAGE_W + e * WSTRIDE + k];
            swd[e * 33 + k] = pack2(v, v);
        }
        __syncthreads();   // px/swd ready; staging free

        if (tile + 1 < NTILES)
            issue_tile(sbase, t, x, w, tok0, (tile + 1) * KT);

        // ---- compute: tile chain of 32 sequential-k FMAs per lane ----
        u64 tacc[4][4];
#pragma unroll
        for (int i = 0; i < 4; i++)
#pragma unroll
            for (int j = 0; j < 4; j++) tacc[i][j] = 0ull;

#pragma unroll 4
        for (int k = 0; k < KT; k++) {
            u64 xv[4], wv[4];
#pragma unroll
            for (int i = 0; i < 4; i++) xv[i] = px[(p0 + i) * 33 + k];
#pragma unroll
            for (int j = 0; j < 4; j++) wv[j] = swd[(eg + 16 * j) * 33 + k];
#pragma unroll
            for (int i = 0; i < 4; i++)
#pragma unroll
                for (int j = 0; j < 4; j++)
                    tacc[i][j] = ffma2(xv[i], wv[j], tacc[i][j]);
        }

        // sequential master fold (same per-lane rounding as round 1)
#pragma unroll
        for (int i = 0; i < 4; i++)
#pragma unroll
            for (int j = 0; j < 4; j++)
                acc[i][j] = fadd2(acc[i][j], tacc[i][j]);
        // no sync here: loop-top sync (after wait_group) orders compute
        // before the next repack overwrites px/swd
    }

    __syncthreads();
    // ---- dump logits to shared (GEMM buffers dead) ----
    float* slog = smem;
#pragma unroll
    for (int i = 0; i < 4; i++)
#pragma unroll
        for (int j = 0; j < 4; j++) {
            float2 v = *reinterpret_cast<float2*>(&acc[i][j]);
            int p = p0 + i;
            slog[(2 * p)     * SLOG_STRIDE + (eg + 16 * j)] = v.x;
            slog[(2 * p + 1) * SLOG_STRIDE + (eg + 16 * j)] = v.y;
        }
    __syncthreads();

    // ---- per-token softmax + bias-corrected top-8 (threads 0..127) ----
    if (t < BT) {
        const int token = tok0 + t;
        float* lg = slog + t * SLOG_STRIDE;

        float mx = lg[0];
#pragma unroll
        for (int e = 1; e < NEXP; e++) mx = fmaxf(mx, lg[e]);

        float sum = 0.0f;
#pragma unroll
        for (int e = 0; e < NEXP; e++) {
            float v = expf(lg[e] - mx);
            lg[e] = v;
            sum += v;
        }
        const float inv = 1.0f / sum;

        unsigned long long used = 0ull;
#pragma unroll
        for (int i = 0; i < TOPK; i++) {
            float best = -INFINITY;
            int bi = 0;
            for (int e = 0; e < NEXP; e++) {
                if ((used >> e) & 1ull) continue;
                float b = lg[e] * inv + sb[e];        // selection uses biased score
                if (b > best) { best = b; bi = e; }   // strict >: lowest index wins
            }
            used |= (1ull << bi);
            out[(size_t)token * TOPK + i] = lg[bi] * inv * ROUTER_SCALE;
            out[(size_t)TOKENS * TOPK + (size_t)token * TOPK + i] = (float)bi;
        }
    }
}

extern "C" void kernel_launch(void* const* d_in, const int* in_sizes, int n_in,
                              void* d_out, int out_size)
{
    const float* x    = (const float*)d_in[0];
    const float* w    = (const float*)d_in[1];
    const float* bias = (const float*)d_in[2];
    float* out = (float*)d_out;

    cudaFuncSetAttribute(gate_kernel,
                         cudaFuncAttributeMaxDynamicSharedMemorySize,
                         SMEM_FLOATS * sizeof(float));

    dim3 grid(TOKENS / BT);   // 1024
    dim3 block(NTHREADS);
    gate_kernel<<<grid, block, SMEM_FLOATS * sizeof(float)>>>(x, w, bias, out);
}

// round 6
// speedup vs baseline: 1.0367x; 1.0108x over previous
#include <cuda_runtime.h>
#include <math.h>
#include <stdint.h>

#define TOKENS 131072
#define HIDDEN 2048
#define NEXP 64
#define TOPK 8
#define ROUTER_SCALE 2.5f

#define BT 128             // tokens per CTA
#define KT 32              // K tile (round-1 numerics)
#define NTHREADS 256
#define NTILES (HIDDEN / KT)   // 64

// SMEM float offsets
//  staging (cp.async): sxs[128][36] | sws[64][36]   = 6912 floats
//  px  (u64, k-major): px[k*64 + p]  = {x[2p][k], x[2p+1][k]}   2048 u64
//  swd (u64, k-major): swd[k*64 + e] = {w[e][k], w[e][k]}       2048 u64
//  epilogue slog[128][65] = 8320 floats reuses [0, 8320)
#define XSTRIDE 36
#define WSTRIDE 36
#define STAGE_X 0
#define STAGE_W (BT * XSTRIDE)                  // 4608
#define STAGE_FLOATS (STAGE_W + NEXP * WSTRIDE) // 6912
#define PX_OFF_F  STAGE_FLOATS                  // 6912 floats = 27648 B (16B ok)
#define SWD_OFF_F (PX_OFF_F + 4096)             // 11008
#define SMEM_FLOATS (SWD_OFF_F + 4096)          // 15104 floats = 60416 B
#define SLOG_STRIDE 65

typedef unsigned long long u64;

__device__ __forceinline__ u64 ffma2(u64 a, u64 b, u64 c) {
    u64 d;
    asm("fma.rn.f32x2 %0, %1, %2, %3;" : "=l"(d) : "l"(a), "l"(b), "l"(c));
    return d;
}
__device__ __forceinline__ u64 fadd2(u64 a, u64 b) {
    u64 d;
    asm("add.rn.f32x2 %0, %1, %2;" : "=l"(d) : "l"(a), "l"(b));
    return d;
}
__device__ __forceinline__ void cpasync16(uint32_t dst_smem, const void* gsrc) {
    asm volatile("cp.async.ca.shared.global [%0], [%1], 16;"
                 :: "r"(dst_smem), "l"(gsrc));
}

__device__ __forceinline__ void issue_tile(uint32_t sbase, int t,
                                           const float* __restrict__ x,
                                           const float* __restrict__ w,
                                           int tok0, int k0) {
    // x tile: 128 rows x 8 float4 = 1024 chunks, 4 per thread
#pragma unroll
    for (int i = 0; i < 4; i++) {
        int idx = t + i * NTHREADS;
        int row = idx >> 3;
        int kq  = idx & 7;
        cpasync16(sbase + (uint32_t)(STAGE_X + row * XSTRIDE + kq * 4) * 4,
                  x + (size_t)(tok0 + row) * HIDDEN + k0 + kq * 4);
    }
    // w tile: 64 rows x 8 float4 = 512 chunks, 2 per thread
#pragma unroll
    for (int i = 0; i < 2; i++) {
        int idx = t + i * NTHREADS;
        int row = idx >> 3;
        int kq  = idx & 7;
        cpasync16(sbase + (uint32_t)(STAGE_W + row * WSTRIDE + kq * 4) * 4,
                  w + (size_t)row * HIDDEN + k0 + kq * 4);
    }
    asm volatile("cp.async.commit_group;" ::: "memory");
}

__global__ __launch_bounds__(NTHREADS, 2)
void gate_kernel(const float* __restrict__ x,
                 const float* __restrict__ w,
                 const float* __restrict__ bias,
                 float* __restrict__ out)
{
    extern __shared__ float smem[];
    __shared__ float sb[NEXP];

    u64* px  = reinterpret_cast<u64*>(smem + PX_OFF_F);
    u64* swd = reinterpret_cast<u64*>(smem + SWD_OFF_F);

    const int t = threadIdx.x;
    const int tok0 = blockIdx.x * BT;

    // thread tile: 4 token-pairs (consecutive: p0..p0+3) x 4 experts (stride 16)
    const int tg = t >> 4;          // 0..15 -> pairs tg*4..tg*4+3
    const int eg = t & 15;          // experts eg, eg+16, eg+32, eg+48
    const int p0 = tg * 4;

    // repack assignment: this thread owns pair/expert column rp for 8 k's
    const int rp = t & 63;          // pair index (px) / expert index (swd)
    const int rk = (t >> 6) * 8;    // k base: 0,8,16,24

    if (t < NEXP) sb[t] = bias[t];

    uint32_t sbase;
    asm("{ .reg .u64 tmp; cvta.to.shared.u64 tmp, %1; cvt.u32.u64 %0, tmp; }"
        : "=r"(sbase) : "l"(smem));

    // master accumulators: lanes = (token 2p, token 2p+1); per-lane op order
    // is EXACTLY round-1's scalar order (bit-identical logits).
    u64 acc[4][4];
#pragma unroll
    for (int i = 0; i < 4; i++)
#pragma unroll
        for (int j = 0; j < 4; j++) acc[i][j] = 0ull;

    issue_tile(sbase, t, x, w, tok0, 0);   // prologue

    for (int tile = 0; tile < NTILES; tile++) {
        asm volatile("cp.async.wait_group 0;" ::: "memory");
        __syncthreads();   // staging ready; also fences last tile's compute

        // ---- repack staging -> px (k-major token pairs) ----
        {
            const float* ra = smem + STAGE_X + (2 * rp) * XSTRIDE + rk;
            const float* rb = ra + XSTRIDE;
            float4 a0 = *(const float4*)(ra);
            float4 a1 = *(const float4*)(ra + 4);
            float4 b0 = *(const float4*)(rb);
            float4 b1 = *(const float4*)(rb + 4);
            float alo[8] = {a0.x, a0.y, a0.z, a0.w, a1.x, a1.y, a1.z, a1.w};
            float bhi[8] = {b0.x, b0.y, b0.z, b0.w, b1.x, b1.y, b1.z, b1.w};
#pragma unroll
            for (int i = 0; i < 8; i++)
                *reinterpret_cast<float2*>(px + (rk + i) * 64 + rp) =
                    make_float2(alo[i], bhi[i]);
        }
        // ---- repack staging -> swd (k-major duplicated weights) ----
        {
            const float* rw = smem + STAGE_W + rp * WSTRIDE + rk;
            float4 c0 = *(const float4*)(rw);
            float4 c1 = *(const float4*)(rw + 4);
            float cv[8] = {c0.x, c0.y, c0.z, c0.w, c1.x, c1.y, c1.z, c1.w};
#pragma unroll
            for (int i = 0; i < 8; i++)
                *reinterpret_cast<float2*>(swd + (rk + i) * 64 + rp) =
                    make_float2(cv[i], cv[i]);
        }
        __syncthreads();   // px/swd ready; staging free

        if (tile + 1 < NTILES)
            issue_tile(sbase, t, x, w, tok0, (tile + 1) * KT);

        // ---- compute: 32 sequential-k FMAs per lane per accumulator ----
        u64 tacc[4][4];
#pragma unroll
        for (int i = 0; i < 4; i++)
#pragma unroll
            for (int j = 0; j < 4; j++) tacc[i][j] = 0ull;

#pragma unroll 4
        for (int k = 0; k < KT; k++) {
            const u64* pk = px + k * 64;
            const u64* wk = swd + k * 64;
            ulonglong2 xa = *(const ulonglong2*)(pk + p0);      // pairs p0,p0+1
            ulonglong2 xb = *(const ulonglong2*)(pk + p0 + 2);  // pairs p0+2,p0+3
            u64 xv[4] = {xa.x, xa.y, xb.x, xb.y};
            u64 wv[4];
#pragma unroll
            for (int j = 0; j < 4; j++) wv[j] = wk[eg + 16 * j];
#pragma unroll
            for (int i = 0; i < 4; i++)
#pragma unroll
                for (int j = 0; j < 4; j++)
                    tacc[i][j] = ffma2(xv[i], wv[j], tacc[i][j]);
        }

        // sequential master fold (same per-lane rounding as round 1)
#pragma unroll
        for (int i = 0; i < 4; i++)
#pragma unroll
            for (int j = 0; j < 4; j++)
                acc[i][j] = fadd2(acc[i][j], tacc[i][j]);
        // loop-top sync (after wait_group) orders compute before next repack
    }

    __syncthreads();
    // ---- dump logits to shared (GEMM buffers dead) ----
    float* slog = smem;
#pragma unroll
    for (int i = 0; i < 4; i++)
#pragma unroll
        for (int j = 0; j < 4; j++) {
            float2 v = *reinterpret_cast<float2*>(&acc[i][j]);
            int p = p0 + i;
            slog[(2 * p)     * SLOG_STRIDE + (eg + 16 * j)] = v.x;
            slog[(2 * p + 1) * SLOG_STRIDE + (eg + 16 * j)] = v.y;
        }
    __syncthreads();

    // ---- per-token softmax + bias-corrected top-8 (threads 0..127) ----
    if (t < BT) {
        const int token = tok0 + t;
        float* lg = slog + t * SLOG_STRIDE;

        float mx = lg[0];
#pragma unroll
        for (int e = 1; e < NEXP; e++) mx = fmaxf(mx, lg[e]);

        float sum = 0.0f;
#pragma unroll
        for (int e = 0; e < NEXP; e++) {
            float v = expf(lg[e] - mx);
            lg[e] = v;
            sum += v;
        }
        const float inv = 1.0f / sum;

        unsigned long long used = 0ull;
#pragma unroll
        for (int i = 0; i < TOPK; i++) {
            float best = -INFINITY;
            int bi = 0;
            for (int e = 0; e < NEXP; e++) {
                if ((used >> e) & 1ull) continue;
                float b = lg[e] * inv + sb[e];        // selection uses biased score
                if (b > best) { best = b; bi = e; }   // strict >: lowest index wins
            }
            used |= (1ull << bi);
            out[(size_t)token * TOPK + i] = lg[bi] * inv * ROUTER_SCALE;
            out[(size_t)TOKENS * TOPK + (size_t)token * TOPK + i] = (float)bi;
        }
    }
}

extern "C" void kernel_launch(void* const* d_in, const int* in_sizes, int n_in,
                              void* d_out, int out_size)
{
    const float* x    = (const float*)d_in[0];
    const float* w    = (const float*)d_in[1];
    const float* bias = (const float*)d_in[2];
    float* out = (float*)d_out;

    cudaFuncSetAttribute(gate_kernel,
                         cudaFuncAttributeMaxDynamicSharedMemorySize,
                         SMEM_FLOATS * sizeof(float));

    dim3 grid(TOKENS / BT);   // 1024
    dim3 block(NTHREADS);
    gate_kernel<<<grid, block, SMEM_FLOATS * sizeof(float)>>>(x, w, bias, out);
}

// round 17
// speedup vs baseline: 1.3244x; 1.2776x over previous
#include <cuda_runtime.h>
#include <math.h>
#include <stdint.h>

#define TOKENS 131072
#define HIDDEN 2048
#define NEXP 64
#define TOPK 8
#define ROUTER_SCALE 2.5f

#define BT 128             // tokens per CTA
#define KT 32              // K tile == accumulation chunk
#define NTHREADS 256
#define NTILES (HIDDEN / KT)   // 64

#define SM_BIAS 0
#define SM_STAGE 1024
#define XS 36
#define STAGE_X_BYTES (128 * XS * 4)                  // 18432
#define STAGE_BYTES   (STAGE_X_BYTES + 64 * XS * 4)   // 27648
#define SMEM_TOTAL    (SM_STAGE + 2 * STAGE_BYTES)    // 56320 B
#define SLOG_STRIDE 66

__device__ __forceinline__ uint32_t f2tf32(float f) {
    uint32_t r;
    asm("cvt.rna.tf32.f32 %0, %1;" : "=r"(r) : "f"(f));
    return r;
}

// d += A(16x8 tf32) * B(8x8 tf32), fp32 accumulate (legacy mma path, sm_80+)
__device__ __forceinline__ void mma8(float* d, const uint32_t* a, const uint32_t* b) {
    asm("mma.sync.aligned.m16n8k8.row.col.f32.tf32.tf32.f32 "
        "{%0,%1,%2,%3}, {%4,%5,%6,%7}, {%8,%9}, {%0,%1,%2,%3};"
        : "+f"(d[0]), "+f"(d[1]), "+f"(d[2]), "+f"(d[3])
        : "r"(a[0]), "r"(a[1]), "r"(a[2]), "r"(a[3]), "r"(b[0]), "r"(b[1]));
}

__device__ __forceinline__ void cpasync16(uint32_t dst, const void* src) {
    asm volatile("cp.async.ca.shared.global [%0], [%1], 16;" :: "r"(dst), "l"(src));
}

__device__ __forceinline__ void issue_stage(uint32_t sbase, int t,
                                            const float* __restrict__ x,
                                            const float* __restrict__ w,
                                            int tok0, int tile) {
    uint32_t sb = sbase + SM_STAGE + (uint32_t)(tile & 1) * STAGE_BYTES;
    int k0 = tile * KT;
#pragma unroll
    for (int i = 0; i < 4; i++) {                  // x: 128 x 8 float4
        int idx = t + i * NTHREADS;
        int row = idx >> 3;
        int kq  = idx & 7;
        cpasync16(sb + (uint32_t)(row * XS + kq * 4) * 4,
                  x + (size_t)(tok0 + row) * HIDDEN + k0 + kq * 4);
    }
#pragma unroll
    for (int i = 0; i < 2; i++) {                  // w: 64 x 8 float4
        int idx = t + i * NTHREADS;
        int row = idx >> 3;
        int kq  = idx & 7;
        cpasync16(sb + STAGE_X_BYTES + (uint32_t)(row * XS + kq * 4) * 4,
                  w + (size_t)row * HIDDEN + k0 + kq * 4);
    }
    asm volatile("cp.async.commit_group;" ::: "memory");
}

__global__ __launch_bounds__(NTHREADS)
void gate_kernel(const float* __restrict__ x,
                 const float* __restrict__ w,
                 const float* __restrict__ bias,
                 float* __restrict__ out)
{
    extern __shared__ char smem[];
    uint32_t sbase;
    asm("{ .reg .u64 tmp; cvta.to.shared.u64 tmp, %1; cvt.u32.u64 %0, tmp; }"
        : "=r"(sbase) : "l"(smem));

    const int t    = threadIdx.x;
    const int wrp  = t >> 5;
    const int lane = t & 31;
    const int gid  = lane >> 2;   // 0..7
    const int tc   = lane & 3;    // 0..3
    const int tok0 = blockIdx.x * BT;

    const int mrow0 = (wrp & 3) * 32;   // warp m-rows
    const int nb0   = (wrp >> 2) * 32;  // warp n-cols

    float* sbias = (float*)(smem + SM_BIAS);
    if (t < NEXP) sbias[t] = bias[t];

    float accm[2][4][4];   // master: RN fp32, folded once per K=32 chunk
#pragma unroll
    for (int mt = 0; mt < 2; mt++)
#pragma unroll
        for (int nt = 0; nt < 4; nt++)
#pragma unroll
            for (int r = 0; r < 4; r++) accm[mt][nt][r] = 0.0f;

    issue_stage(sbase, t, x, w, tok0, 0);

    for (int tile = 0; tile < NTILES; tile++) {
        __syncthreads();   // prior compute done -> safe to refill other buffer
        if (tile + 1 < NTILES) {
            issue_stage(sbase, t, x, w, tok0, tile + 1);
            asm volatile("cp.async.wait_group 1;" ::: "memory");
        } else {
            asm volatile("cp.async.wait_group 0;" ::: "memory");
        }
        __syncthreads();   // staging[tile&1] visible

        const float* sx  = (const float*)(smem + SM_STAGE + (tile & 1) * STAGE_BYTES);
        const float* sw_ = sx + 128 * XS;

        // per-chunk accumulator: zeroed each tile so in-tensor-core RZ chains
        // stay short (16 mma at small magnitude); folded into master in RN
        float accc[2][4][4];
#pragma unroll
        for (int mt = 0; mt < 2; mt++)
#pragma unroll
            for (int nt = 0; nt < 4; nt++)
#pragma unroll
                for (int r = 0; r < 4; r++) accc[mt][nt][r] = 0.0f;

        for (int kc = 0; kc < 4; kc++) {          // 4 k-chunks of 8
            uint32_t ah[2][4], al[2][4];
#pragma unroll
            for (int mt = 0; mt < 2; mt++) {
                const float* p0 = sx + (mrow0 + mt * 16 + gid) * XS + kc * 8 + tc;
                const float* p1 = p0 + 8 * XS;
                float f0 = p0[0], f1 = p1[0], f2 = p0[4], f3 = p1[4];
                ah[mt][0] = f2tf32(f0); al[mt][0] = f2tf32(f0 - __uint_as_float(ah[mt][0]));
                ah[mt][1] = f2tf32(f1); al[mt][1] = f2tf32(f1 - __uint_as_float(ah[mt][1]));
                ah[mt][2] = f2tf32(f2); al[mt][2] = f2tf32(f2 - __uint_as_float(ah[mt][2]));
                ah[mt][3] = f2tf32(f3); al[mt][3] = f2tf32(f3 - __uint_as_float(ah[mt][3]));
            }
            uint32_t bh[4][2], bl[4][2];
#pragma unroll
            for (int nt = 0; nt < 4; nt++) {
                const float* pb = sw_ + (nb0 + nt * 8 + gid) * XS + kc * 8 + tc;
                float g0 = pb[0], g1 = pb[4];
                bh[nt][0] = f2tf32(g0); bl[nt][0] = f2tf32(g0 - __uint_as_float(bh[nt][0]));
                bh[nt][1] = f2tf32(g1); bl[nt][1] = f2tf32(g1 - __uint_as_float(bh[nt][1]));
            }
            // 4-pass exact product: hh + hl + lh + ll
#pragma unroll
            for (int mt = 0; mt < 2; mt++)
#pragma unroll
                for (int nt = 0; nt < 4; nt++) {
                    mma8(accc[mt][nt], ah[mt], bh[nt]);
                    mma8(accc[mt][nt], ah[mt], bl[nt]);
                    mma8(accc[mt][nt], al[mt], bh[nt]);
                    mma8(accc[mt][nt], al[mt], bl[nt]);
                }
        }

        // sequential RN fold of the chunk into the master (R1-style two-level)
#pragma unroll
        for (int mt = 0; mt < 2; mt++)
#pragma unroll
            for (int nt = 0; nt < 4; nt++)
#pragma unroll
                for (int r = 0; r < 4; r++)
                    accm[mt][nt][r] += accc[mt][nt][r];
    }

    // ---- epilogue: logits -> smem (reuses staging), softmax + top-8 ----
    __syncthreads();
    float* slog = (float*)(smem + SM_STAGE);
#pragma unroll
    for (int mt = 0; mt < 2; mt++)
#pragma unroll
        for (int nt = 0; nt < 4; nt++) {
            int r = mrow0 + mt * 16 + gid;
            int c = nb0 + nt * 8 + 2 * tc;
            *(float2*)(slog + r * SLOG_STRIDE + c) =
                make_float2(accm[mt][nt][0], accm[mt][nt][1]);
            *(float2*)(slog + (r + 8) * SLOG_STRIDE + c) =
                make_float2(accm[mt][nt][2], accm[mt][nt][3]);
        }
    __syncthreads();

    if (t < BT) {
        const int token = tok0 + t;
        float* lg = slog + t * SLOG_STRIDE;

        float mx = lg[0];
#pragma unroll
        for (int e = 1; e < NEXP; e++) mx = fmaxf(mx, lg[e]);

        float sum = 0.0f;
#pragma unroll
        for (int e = 0; e < NEXP; e++) {
            float v = expf(lg[e] - mx);
            lg[e] = v;
            sum += v;
        }
        const float inv = 1.0f / sum;

        unsigned long long used = 0ull;
#pragma unroll
        for (int i = 0; i < TOPK; i++) {
            float best = -INFINITY;
            int bi = 0;
            for (int e = 0; e < NEXP; e++) {
                if ((used >> e) & 1ull) continue;
                float bsc = lg[e] * inv + sbias[e];     // selection uses biased score
                if (bsc > best) { best = bsc; bi = e; } // strict >: lowest index wins
            }
            used |= (1ull << bi);
            out[(size_t)token * TOPK + i] = lg[bi] * inv * ROUTER_SCALE;
            out[(size_t)TOKENS * TOPK + (size_t)token * TOPK + i] = (float)bi;
        }
    }
}

extern "C" void kernel_launch(void* const* d_in, const int* in_sizes, int n_in,
                              void* d_out, int out_size)
{
    const float* x    = (const float*)d_in[0];
    const float* w    = (const float*)d_in[1];
    const float* bias = (const float*)d_in[2];
    float* out = (float*)d_out;

    cudaFuncSetAttribute(gate_kernel,
                         cudaFuncAttributeMaxDynamicSharedMemorySize, SMEM_TOTAL);

    dim3 grid(TOKENS / BT);   // 1024
    dim3 block(NTHREADS);
    gate_kernel<<<grid, block, SMEM_TOTAL>>>(x, w, bias, out);
}